// round 8
// baseline (speedup 1.0000x reference)
#include <cuda_runtime.h>
#include <cuda_fp16.h>
#include <cuda_bf16.h>

#define RES   256
#define RANK  12
#define OUTC  8

#define HU(h)  (*(unsigned int*)&(h))
#define U2H(u) (*(__half2*)&(u))

// Corner-quad records: per (plane,y,x) a 64B record {v00,v01,v10,v11} of
// fp16x8 projected features (+ bias/3 folded in), border clamp baked. 12 MB.
__device__ uint4 g_planes_q[3 * RES * RES * 4];

// ---------------------------------------------------------------------------
// Prolog (tiled): one block = 16x16 output tile. Project the 17x17 halo tile
// into smem ONCE per texel (bias/3 added), then emit 256 quad records.
// ---------------------------------------------------------------------------
__global__ void __launch_bounds__(256)
build_quads_kernel(const float* __restrict__ pxy,
                   const float* __restrict__ pxz,
                   const float* __restrict__ pyz,
                   const float* __restrict__ W,
                   const float* __restrict__ B)
{
    const int p = blockIdx.z;
    const float* __restrict__ src = (p == 0) ? pxy : ((p == 1) ? pxz : pyz);

    __shared__ float w[OUTC][RANK];
    __shared__ float b3[OUTC];
    __shared__ uint4 tile[17][17];

    int tid = threadIdx.x;
    if (tid < OUTC * RANK) {
        int o = tid / RANK, k = tid % RANK;
        w[o][k] = W[o * (3 * RANK) + p * RANK + k];
    }
    if (tid < OUTC) b3[tid] = B[tid] * (1.f / 3.f);
    __syncthreads();

    int bx = blockIdx.x * 16;
    int by = blockIdx.y * 16;

    for (int l = tid; l < 17 * 17; l += 256) {
        int dy = l / 17, dx = l % 17;
        int sx = min(bx + dx, RES - 1);
        int sy = min(by + dy, RES - 1);
        const float* in = src + (size_t)(sy * RES + sx) * RANK;
        float4 i0 = __ldg((const float4*)(in));
        float4 i1 = __ldg((const float4*)(in + 4));
        float4 i2 = __ldg((const float4*)(in + 8));
        float f[RANK] = { i0.x,i0.y,i0.z,i0.w, i1.x,i1.y,i1.z,i1.w,
                          i2.x,i2.y,i2.z,i2.w };
        float o[OUTC];
        #pragma unroll
        for (int c = 0; c < OUTC; c++) {
            float s = b3[c];
            #pragma unroll
            for (int k = 0; k < RANK; k++) s = fmaf(f[k], w[c][k], s);
            o[c] = s;
        }
        __half2 h0 = __floats2half2_rn(o[0], o[1]);
        __half2 h1 = __floats2half2_rn(o[2], o[3]);
        __half2 h2 = __floats2half2_rn(o[4], o[5]);
        __half2 h3 = __floats2half2_rn(o[6], o[7]);
        uint4 r;
        r.x = HU(h0); r.y = HU(h1); r.z = HU(h2); r.w = HU(h3);
        tile[dy][dx] = r;
    }
    __syncthreads();

    int dx = tid & 15, dy = tid >> 4;
    int texel = (by + dy) * RES + (bx + dx);
    uint4* dst = &g_planes_q[((size_t)((p << 16) | texel)) << 2];
    dst[0] = tile[dy    ][dx    ];
    dst[1] = tile[dy    ][dx + 1];
    dst[2] = tile[dy + 1][dx    ];
    dst[3] = tile[dy + 1][dx + 1];
}

// ---------------------------------------------------------------------------
// Main kernel: 4 lanes per 2 points; lane c = corner c of both points.
// Each plane sample = ONE LDG.128 into a 64B-aligned quad -> 1 wavefront.
// Quad reduction via smem (144B/group stride, LDS phase conflict-free).
// ---------------------------------------------------------------------------
__device__ __forceinline__ void point_accum(float cx, float cy, float cz,
                                            int c, float sx, float ox,
                                            float sy, float oy,
                                            __half2 acc[4])
{
    // unnormalize + clamp via FFMA.SAT (subsumes coord clip)
    float tx = 255.f * __saturatef(fmaf(cx, 128.f / 255.f, 0.5f));
    float ty = 255.f * __saturatef(fmaf(cy, 128.f / 255.f, 0.5f));
    float tz = 255.f * __saturatef(fmaf(cz, 128.f / 255.f, 0.5f));
    float fx = floorf(tx), fy = floorf(ty), fz = floorf(tz);
    float wx = tx - fx, wy = ty - fy, wz = tz - fz;
    int x0 = (int)fx, y0 = (int)fy, z0 = (int)fz;

    // lane-side weights: first-axis uses corner bit0 (sx,ox), second-axis bit1
    float u_x = fmaf(sx, wx, ox);   // x as first axis (planes xy, xz)
    float u_y = fmaf(sx, wy, ox);   // y as first axis (plane yz)
    float v_y = fmaf(sy, wy, oy);   // y as second axis (plane xy)
    float v_z = fmaf(sy, wz, oy);   // z as second axis (planes xz, yz)

    __half2 w0 = __float2half2_rn(u_x * v_y);
    __half2 w1 = __float2half2_rn(u_x * v_z);
    __half2 w2 = __float2half2_rn(u_y * v_z);

    int o0 = ((          (y0 << 8) | x0) << 2) + c;
    int o1 = (((1 << 16) | (z0 << 8) | x0) << 2) + c;
    int o2 = (((2 << 16) | (z0 << 8) | y0) << 2) + c;

    uint4 a = __ldg(&g_planes_q[o0]);
    uint4 b = __ldg(&g_planes_q[o1]);
    uint4 d = __ldg(&g_planes_q[o2]);

    acc[0] = __hfma2(U2H(a.x), w0, acc[0]);
    acc[1] = __hfma2(U2H(a.y), w0, acc[1]);
    acc[2] = __hfma2(U2H(a.z), w0, acc[2]);
    acc[3] = __hfma2(U2H(a.w), w0, acc[3]);
    acc[0] = __hfma2(U2H(b.x), w1, acc[0]);
    acc[1] = __hfma2(U2H(b.y), w1, acc[1]);
    acc[2] = __hfma2(U2H(b.z), w1, acc[2]);
    acc[3] = __hfma2(U2H(b.w), w1, acc[3]);
    acc[0] = __hfma2(U2H(d.x), w2, acc[0]);
    acc[1] = __hfma2(U2H(d.y), w2, acc[1]);
    acc[2] = __hfma2(U2H(d.z), w2, acc[2]);
    acc[3] = __hfma2(U2H(d.w), w2, acc[3]);
}

__global__ void __launch_bounds__(256)
geo_encoder_kernel(const float* __restrict__ coords,
                   float* __restrict__ out,
                   int N)
{
    // 64 groups x 144B (9 uint4): [0..3]=A corners, [4..7]=B corners, [8]=pad
    __shared__ uint4 red[64 * 9];

    int t = blockIdx.x * blockDim.x + threadIdx.x;
    int pairs = (N + 1) >> 1;
    int g = t >> 2;              // point-pair index (points 2g, 2g+1)
    int c = t & 3;               // corner: bit0 = x side, bit1 = y side
    int gq = min(g, pairs - 1);  // clamp (keep all threads alive for syncwarp)
    int iA = 2 * gq;
    bool hasB = (iA + 1) < N;

    // coords for both points: 2 lane-loads + 6 narrow shuffles
    size_t base = 6 * (size_t)gq;
    float v0 = (c < 3 || hasB) ? __ldg(coords + base + c) : 0.f;
    float v1 = (c < 2 && hasB) ? __ldg(coords + base + 4 + c) : 0.f;
    float cxA = __shfl_sync(0xffffffffu, v0, 0, 4);
    float cyA = __shfl_sync(0xffffffffu, v0, 1, 4);
    float czA = __shfl_sync(0xffffffffu, v0, 2, 4);
    float cxB = __shfl_sync(0xffffffffu, v0, 3, 4);
    float cyB = __shfl_sync(0xffffffffu, v1, 0, 4);
    float czB = __shfl_sync(0xffffffffu, v1, 1, 4);

    float fxc = (float)(c & 1);
    float fyc = (float)(c >> 1);
    float sx = 2.f * fxc - 1.f, ox = 1.f - fxc;
    float sy = 2.f * fyc - 1.f, oy = 1.f - fyc;

    __half2 z = __float2half2_rn(0.f);
    __half2 accA[4] = { z, z, z, z };
    __half2 accB[4] = { z, z, z, z };

    point_accum(cxA, cyA, czA, c, sx, ox, sy, oy, accA);
    point_accum(cxB, cyB, czB, c, sx, ox, sy, oy, accB);

    // ── smem quad reduction ──
    int lg = threadIdx.x >> 2;
    uint4* gb = &red[lg * 9];
    uint4 ta; ta.x = HU(accA[0]); ta.y = HU(accA[1]); ta.z = HU(accA[2]); ta.w = HU(accA[3]);
    uint4 tb; tb.x = HU(accB[0]); tb.y = HU(accB[1]); tb.z = HU(accB[2]); tb.w = HU(accB[3]);
    gb[c]     = ta;
    gb[4 + c] = tb;
    __syncwarp();

    // lane role: point sel = c>>1 (A/B), channel-half h = c&1
    const uint2* rp = (const uint2*)(gb + ((c >> 1) << 2));
    int hh = c & 1;
    uint2 s0 = rp[0 + hh];
    uint2 s1 = rp[2 + hh];
    uint2 s2 = rp[4 + hh];
    uint2 s3 = rp[6 + hh];

    __half2 r0 = __hadd2(__hadd2(U2H(s0.x), U2H(s1.x)),
                         __hadd2(U2H(s2.x), U2H(s3.x)));
    __half2 r1 = __hadd2(__hadd2(U2H(s0.y), U2H(s1.y)),
                         __hadd2(U2H(s2.y), U2H(s3.y)));

    // clamp [-10,10] in half2, then upconvert
    const __half2 TEN  = __float2half2_rn(10.f);
    const __half2 NTEN = __float2half2_rn(-10.f);
    r0 = __hmax2(__hmin2(r0, TEN), NTEN);
    r1 = __hmax2(__hmin2(r1, TEN), NTEN);

    float2 e0 = __half22float2(r0);
    float2 e1 = __half22float2(r1);

    // lane c writes float4 #c of the pair's 64B output record
    if (g < pairs && (c < 2 || hasB))
        ((float4*)(out + 16 * (size_t)g))[c] = make_float4(e0.x, e0.y, e1.x, e1.y);
}

extern "C" void kernel_launch(void* const* d_in, const int* in_sizes, int n_in,
                              void* d_out, int out_size)
{
    const float* coords = (const float*)d_in[0];
    const float* pxy    = (const float*)d_in[1];
    const float* pxz    = (const float*)d_in[2];
    const float* pyz    = (const float*)d_in[3];
    const float* projw  = (const float*)d_in[4];
    const float* projb  = (const float*)d_in[5];
    float* out = (float*)d_out;

    int N = in_sizes[0] / 3;

    dim3 qgrid(RES / 16, RES / 16, 3);
    build_quads_kernel<<<qgrid, 256>>>(pxy, pxz, pyz, projw, projb);

    long long pairs = (N + 1) / 2;
    long long threads = 4LL * pairs;
    int blocks = (int)((threads + 255) / 256);
    geo_encoder_kernel<<<blocks, 256>>>(coords, out, N);
}

// round 11
// speedup vs baseline: 1.0213x; 1.0213x over previous
#include <cuda_runtime.h>
#include <cuda_fp16.h>
#include <cuda_bf16.h>

#define RES   256
#define RANK  12
#define OUTC  8

#define HU(h)  (*(unsigned int*)&(h))
#define U2H(u) (*(__half2*)&(u))

// Corner-quad records: per (plane,y,x) a 64B record {v00,v01,v10,v11} of
// fp16x8 projected features (+ bias/3 folded in), border clamp baked. 12 MB.
__device__ uint4 g_planes_q[3 * RES * RES * 4];

// ---------------------------------------------------------------------------
// Prolog (tiled): one block = 16x16 output tile. Project the 17x17 halo tile
// into smem ONCE per texel (bias/3 added), then emit 256 quad records.
// ---------------------------------------------------------------------------
__global__ void __launch_bounds__(256)
build_quads_kernel(const float* __restrict__ pxy,
                   const float* __restrict__ pxz,
                   const float* __restrict__ pyz,
                   const float* __restrict__ W,
                   const float* __restrict__ B)
{
    const int p = blockIdx.z;
    const float* __restrict__ src = (p == 0) ? pxy : ((p == 1) ? pxz : pyz);

    __shared__ float w[OUTC][RANK];
    __shared__ float b3[OUTC];
    __shared__ uint4 tile[17][17];

    int tid = threadIdx.x;
    if (tid < OUTC * RANK) {
        int o = tid / RANK, k = tid % RANK;
        w[o][k] = W[o * (3 * RANK) + p * RANK + k];
    }
    if (tid < OUTC) b3[tid] = B[tid] * (1.f / 3.f);
    __syncthreads();

    int bx = blockIdx.x * 16;
    int by = blockIdx.y * 16;

    for (int l = tid; l < 17 * 17; l += 256) {
        int dy = l / 17, dx = l % 17;
        int sx = min(bx + dx, RES - 1);
        int sy = min(by + dy, RES - 1);
        const float* in = src + (size_t)(sy * RES + sx) * RANK;
        float4 i0 = __ldg((const float4*)(in));
        float4 i1 = __ldg((const float4*)(in + 4));
        float4 i2 = __ldg((const float4*)(in + 8));
        float f[RANK] = { i0.x,i0.y,i0.z,i0.w, i1.x,i1.y,i1.z,i1.w,
                          i2.x,i2.y,i2.z,i2.w };
        float o[OUTC];
        #pragma unroll
        for (int c = 0; c < OUTC; c++) {
            float s = b3[c];
            #pragma unroll
            for (int k = 0; k < RANK; k++) s = fmaf(f[k], w[c][k], s);
            o[c] = s;
        }
        __half2 h0 = __floats2half2_rn(o[0], o[1]);
        __half2 h1 = __floats2half2_rn(o[2], o[3]);
        __half2 h2 = __floats2half2_rn(o[4], o[5]);
        __half2 h3 = __floats2half2_rn(o[6], o[7]);
        uint4 r;
        r.x = HU(h0); r.y = HU(h1); r.z = HU(h2); r.w = HU(h3);
        tile[dy][dx] = r;
    }
    __syncthreads();

    int dx = tid & 15, dy = tid >> 4;
    int texel = (by + dy) * RES + (bx + dx);
    uint4* dst = &g_planes_q[((size_t)((p << 16) | texel)) << 2];
    dst[0] = tile[dy    ][dx    ];
    dst[1] = tile[dy    ][dx + 1];
    dst[2] = tile[dy + 1][dx    ];
    dst[3] = tile[dy + 1][dx + 1];
}

// ---------------------------------------------------------------------------
// Main kernel (R7 structure): 4 lanes per 2 points; lane c = corner c of both
// points. Each plane sample = ONE LDG.128 into a 64B-aligned quad -> 1 L1
// wavefront. Reduction via SHFL butterfly (MIO pipe, keeps L1 free).
// ---------------------------------------------------------------------------
__device__ __forceinline__ void point_accum(float cx, float cy, float cz,
                                            int c, float sx, float ox,
                                            float sy, float oy,
                                            __half2 acc[4])
{
    // unnormalize + clamp via FFMA.SAT (subsumes coord clip)
    float tx = 255.f * __saturatef(fmaf(cx, 128.f / 255.f, 0.5f));
    float ty = 255.f * __saturatef(fmaf(cy, 128.f / 255.f, 0.5f));
    float tz = 255.f * __saturatef(fmaf(cz, 128.f / 255.f, 0.5f));
    float fx = floorf(tx), fy = floorf(ty), fz = floorf(tz);
    float wx = tx - fx, wy = ty - fy, wz = tz - fz;
    int x0 = (int)fx, y0 = (int)fy, z0 = (int)fz;

    // lane-side weights: first-axis uses corner bit0 (sx,ox), second-axis bit1
    float u_x = fmaf(sx, wx, ox);   // x as first axis (planes xy, xz)
    float u_y = fmaf(sx, wy, ox);   // y as first axis (plane yz)
    float v_y = fmaf(sy, wy, oy);   // y as second axis (plane xy)
    float v_z = fmaf(sy, wz, oy);   // z as second axis (planes xz, yz)

    __half2 w0 = __float2half2_rn(u_x * v_y);
    __half2 w1 = __float2half2_rn(u_x * v_z);
    __half2 w2 = __float2half2_rn(u_y * v_z);

    int o0 = ((          (y0 << 8) | x0) << 2) + c;
    int o1 = (((1 << 16) | (z0 << 8) | x0) << 2) + c;
    int o2 = (((2 << 16) | (z0 << 8) | y0) << 2) + c;

    uint4 a = __ldg(&g_planes_q[o0]);
    uint4 b = __ldg(&g_planes_q[o1]);
    uint4 d = __ldg(&g_planes_q[o2]);

    acc[0] = __hfma2(U2H(a.x), w0, acc[0]);
    acc[1] = __hfma2(U2H(a.y), w0, acc[1]);
    acc[2] = __hfma2(U2H(a.z), w0, acc[2]);
    acc[3] = __hfma2(U2H(a.w), w0, acc[3]);
    acc[0] = __hfma2(U2H(b.x), w1, acc[0]);
    acc[1] = __hfma2(U2H(b.y), w1, acc[1]);
    acc[2] = __hfma2(U2H(b.z), w1, acc[2]);
    acc[3] = __hfma2(U2H(b.w), w1, acc[3]);
    acc[0] = __hfma2(U2H(d.x), w2, acc[0]);
    acc[1] = __hfma2(U2H(d.y), w2, acc[1]);
    acc[2] = __hfma2(U2H(d.z), w2, acc[2]);
    acc[3] = __hfma2(U2H(d.w), w2, acc[3]);
}

__device__ __forceinline__ __half2 hshfl_add(__half2 v, int lanemask) {
    unsigned int u = HU(v);
    unsigned int s = __shfl_xor_sync(0xffffffffu, u, lanemask);
    return __hadd2(v, U2H(s));
}

__global__ void __launch_bounds__(256)
geo_encoder_kernel(const float* __restrict__ coords,
                   float* __restrict__ out,
                   int N)
{
    int t = blockIdx.x * blockDim.x + threadIdx.x;
    int g = t >> 2;              // point-pair index (points 2g, 2g+1)
    int iA = 2 * g;
    if (iA >= N) return;
    int c = t & 3;               // corner: bit0 = x side, bit1 = y side
    bool hasB = (iA + 1) < N;

    // coords for both points: 2 lane-loads + 6 narrow shuffles
    size_t base = 6 * (size_t)g;
    float v0 = (c < 3 || hasB) ? __ldg(coords + base + c) : 0.f;
    float v1 = (c < 2 && hasB) ? __ldg(coords + base + 4 + c) : 0.f;
    float cxA = __shfl_sync(0xffffffffu, v0, 0, 4);
    float cyA = __shfl_sync(0xffffffffu, v0, 1, 4);
    float czA = __shfl_sync(0xffffffffu, v0, 2, 4);
    float cxB = __shfl_sync(0xffffffffu, v0, 3, 4);
    float cyB = __shfl_sync(0xffffffffu, v1, 0, 4);
    float czB = __shfl_sync(0xffffffffu, v1, 1, 4);

    float fxc = (float)(c & 1);
    float fyc = (float)(c >> 1);
    float sx = 2.f * fxc - 1.f, ox = 1.f - fxc;
    float sy = 2.f * fyc - 1.f, oy = 1.f - fyc;

    __half2 z = __float2half2_rn(0.f);
    __half2 accA[4] = { z, z, z, z };
    __half2 accB[4] = { z, z, z, z };

    point_accum(cxA, cyA, czA, c, sx, ox, sy, oy, accA);
    if (hasB) point_accum(cxB, cyB, czB, c, sx, ox, sy, oy, accB);

    // quad butterfly reduction in half2 (8 shfl+hadd2 per point)
    #pragma unroll
    for (int r = 0; r < 4; r++) {
        accA[r] = hshfl_add(accA[r], 1);
        accA[r] = hshfl_add(accA[r], 2);
        accB[r] = hshfl_add(accB[r], 1);
        accB[r] = hshfl_add(accB[r], 2);
    }

    // lane c writes float4 #c of the pair's 64B output record:
    // c=0: ptA ch0-3, c=1: ptA ch4-7, c=2: ptB ch0-3, c=3: ptB ch4-7
    __half2 s0 = (c & 2) ? accB[(c & 1) * 2]     : accA[(c & 1) * 2];
    __half2 s1 = (c & 2) ? accB[(c & 1) * 2 + 1] : accA[(c & 1) * 2 + 1];

    // clamp [-10,10] in half2, then upconvert (bias already folded into quads)
    const __half2 TEN  = __float2half2_rn(10.f);
    const __half2 NTEN = __float2half2_rn(-10.f);
    s0 = __hmax2(__hmin2(s0, TEN), NTEN);
    s1 = __hmax2(__hmin2(s1, TEN), NTEN);

    float2 f0 = __half22float2(s0);
    float2 f1 = __half22float2(s1);

    if (c < 2 || hasB)
        ((float4*)(out + 16 * (size_t)g))[c] = make_float4(f0.x, f0.y, f1.x, f1.y);
}

extern "C" void kernel_launch(void* const* d_in, const int* in_sizes, int n_in,
                              void* d_out, int out_size)
{
    const float* coords = (const float*)d_in[0];
    const float* pxy    = (const float*)d_in[1];
    const float* pxz    = (const float*)d_in[2];
    const float* pyz    = (const float*)d_in[3];
    const float* projw  = (const float*)d_in[4];
    const float* projb  = (const float*)d_in[5];
    float* out = (float*)d_out;

    int N = in_sizes[0] / 3;

    dim3 qgrid(RES / 16, RES / 16, 3);
    build_quads_kernel<<<qgrid, 256>>>(pxy, pxz, pyz, projw, projb);

    long long pairs = (N + 1) / 2;
    long long threads = 4LL * pairs;
    int blocks = (int)((threads + 255) / 256);
    geo_encoder_kernel<<<blocks, 256>>>(coords, out, N);
}

// round 13
// speedup vs baseline: 1.0800x; 1.0575x over previous
#include <cuda_runtime.h>
#include <cuda_fp16.h>
#include <cuda_bf16.h>

#define RES   256
#define RANK  12
#define OUTC  8

#define HU(h)  (*(unsigned int*)&(h))
#define U2H(u) (*(__half2*)&(u))

// Corner-quad records: per (plane,y,x) a 64B record {v00,v01,v10,v11} of
// fp16x8 projected features (+ bias/3 folded in), border clamp baked. 12 MB.
__device__ uint4 g_planes_q[3 * RES * RES * 4];

// ---------------------------------------------------------------------------
// Prolog (tiled): one block = 16x16 output tile. Project the 17x17 halo tile
// into smem ONCE per texel (bias/3 added), then emit 256 quad records with a
// corner-transposed loop so each warp stores 512B contiguous (4 wf/STG).
// Tile row stride 19 uint4 (304B = 48 mod 128) -> corner LDS phases hit
// banks {0,16,32,48,64,80}: conflict-free.
// ---------------------------------------------------------------------------
__global__ void __launch_bounds__(256)
build_quads_kernel(const float* __restrict__ pxy,
                   const float* __restrict__ pxz,
                   const float* __restrict__ pyz,
                   const float* __restrict__ W,
                   const float* __restrict__ B)
{
    const int p = blockIdx.z;
    const float* __restrict__ src = (p == 0) ? pxy : ((p == 1) ? pxz : pyz);

    __shared__ float w[OUTC][RANK];
    __shared__ float b3[OUTC];
    __shared__ uint4 tile[17][19];   // padded stride for conflict-free reads

    int tid = threadIdx.x;
    if (tid < OUTC * RANK) {
        int o = tid / RANK, k = tid % RANK;
        w[o][k] = W[o * (3 * RANK) + p * RANK + k];
    }
    if (tid < OUTC) b3[tid] = B[tid] * (1.f / 3.f);
    __syncthreads();

    int bx = blockIdx.x * 16;
    int by = blockIdx.y * 16;

    for (int l = tid; l < 17 * 17; l += 256) {
        int dy = l / 17, dx = l % 17;
        int sx = min(bx + dx, RES - 1);
        int sy = min(by + dy, RES - 1);
        const float* in = src + (size_t)(sy * RES + sx) * RANK;
        float4 i0 = __ldg((const float4*)(in));
        float4 i1 = __ldg((const float4*)(in + 4));
        float4 i2 = __ldg((const float4*)(in + 8));
        float f[RANK] = { i0.x,i0.y,i0.z,i0.w, i1.x,i1.y,i1.z,i1.w,
                          i2.x,i2.y,i2.z,i2.w };
        float o[OUTC];
        #pragma unroll
        for (int c = 0; c < OUTC; c++) {
            float s = b3[c];
            #pragma unroll
            for (int k = 0; k < RANK; k++) s = fmaf(f[k], w[c][k], s);
            o[c] = s;
        }
        __half2 h0 = __floats2half2_rn(o[0], o[1]);
        __half2 h1 = __floats2half2_rn(o[2], o[3]);
        __half2 h2 = __floats2half2_rn(o[4], o[5]);
        __half2 h3 = __floats2half2_rn(o[6], o[7]);
        uint4 r;
        r.x = HU(h0); r.y = HU(h1); r.z = HU(h2); r.w = HU(h3);
        tile[dy][dx] = r;
    }
    __syncthreads();

    // corner-transposed emit: thread = (texel, corner); warp writes 512B contig
    int c  = tid & 3;            // corner: bit0 = x side, bit1 = y side
    int t0 = tid >> 2;           // first texel handled by this thread
    #pragma unroll
    for (int i = 0; i < 4; i++) {
        int tex = t0 + i * 64;           // 0..255 within tile
        int dx = tex & 15, dy = tex >> 4;
        uint4 v = tile[dy + (c >> 1)][dx + (c & 1)];
        int texel = (by + dy) * RES + (bx + dx);
        g_planes_q[((((size_t)((p << 16) | texel)) << 2)) + c] = v;
    }
}

// ---------------------------------------------------------------------------
// Main kernel: 4 lanes per 2 points; lane c = corner c of both points.
// All 6 gather LDGs batched up front for MLP; each is ONE L1 wavefront.
// ---------------------------------------------------------------------------
struct Coord3 { float x, y, z; };

__device__ __forceinline__ void coord_setup(float cx, float cy, float cz,
                                            float sx, float ox, float sy, float oy,
                                            int c,
                                            int& o0, int& o1, int& o2,
                                            __half2& w0, __half2& w1, __half2& w2)
{
    // unnormalize + clamp via FFMA.SAT (subsumes coord clip)
    float tx = 255.f * __saturatef(fmaf(cx, 128.f / 255.f, 0.5f));
    float ty = 255.f * __saturatef(fmaf(cy, 128.f / 255.f, 0.5f));
    float tz = 255.f * __saturatef(fmaf(cz, 128.f / 255.f, 0.5f));
    float fx = floorf(tx), fy = floorf(ty), fz = floorf(tz);
    float wx = tx - fx, wy = ty - fy, wz = tz - fz;
    int x0 = (int)fx, y0 = (int)fy, z0 = (int)fz;

    float u_x = fmaf(sx, wx, ox);
    float u_y = fmaf(sx, wy, ox);
    float v_y = fmaf(sy, wy, oy);
    float v_z = fmaf(sy, wz, oy);

    w0 = __float2half2_rn(u_x * v_y);   // xy
    w1 = __float2half2_rn(u_x * v_z);   // xz
    w2 = __float2half2_rn(u_y * v_z);   // yz

    o0 = ((          (y0 << 8) | x0) << 2) + c;
    o1 = (((1 << 16) | (z0 << 8) | x0) << 2) + c;
    o2 = (((2 << 16) | (z0 << 8) | y0) << 2) + c;
}

__device__ __forceinline__ void fma_quad(__half2 acc[4], uint4 u, __half2 w) {
    acc[0] = __hfma2(U2H(u.x), w, acc[0]);
    acc[1] = __hfma2(U2H(u.y), w, acc[1]);
    acc[2] = __hfma2(U2H(u.z), w, acc[2]);
    acc[3] = __hfma2(U2H(u.w), w, acc[3]);
}

__device__ __forceinline__ __half2 hshfl_add(__half2 v, int lanemask) {
    unsigned int u = HU(v);
    unsigned int s = __shfl_xor_sync(0xffffffffu, u, lanemask);
    return __hadd2(v, U2H(s));
}

__global__ void __launch_bounds__(256, 6)
geo_encoder_kernel(const float* __restrict__ coords,
                   float* __restrict__ out,
                   int N)
{
    int t = blockIdx.x * blockDim.x + threadIdx.x;
    int g = t >> 2;              // point-pair index (points 2g, 2g+1)
    int iA = 2 * g;
    if (iA >= N) return;
    int c = t & 3;               // corner: bit0 = x side, bit1 = y side
    bool hasB = (iA + 1) < N;

    // coords for both points: 2 lane-loads + 6 narrow shuffles
    size_t base = 6 * (size_t)g;
    float v0 = (c < 3 || hasB) ? __ldg(coords + base + c) : 0.f;
    float v1 = (c < 2 && hasB) ? __ldg(coords + base + 4 + c) : 0.f;
    float cxA = __shfl_sync(0xffffffffu, v0, 0, 4);
    float cyA = __shfl_sync(0xffffffffu, v0, 1, 4);
    float czA = __shfl_sync(0xffffffffu, v0, 2, 4);
    float cxB = __shfl_sync(0xffffffffu, v0, 3, 4);
    float cyB = __shfl_sync(0xffffffffu, v1, 0, 4);
    float czB = __shfl_sync(0xffffffffu, v1, 1, 4);
    if (!hasB) { cxB = cxA; cyB = cyA; czB = czA; }   // safe dup for dead point

    float fxc = (float)(c & 1);
    float fyc = (float)(c >> 1);
    float sx = 2.f * fxc - 1.f, ox = 1.f - fxc;
    float sy = 2.f * fyc - 1.f, oy = 1.f - fyc;

    // offsets + weights for both points, then ALL SIX loads batched (MLP=6)
    int oA0, oA1, oA2, oB0, oB1, oB2;
    __half2 wA0, wA1, wA2, wB0, wB1, wB2;
    coord_setup(cxA, cyA, czA, sx, ox, sy, oy, c, oA0, oA1, oA2, wA0, wA1, wA2);
    coord_setup(cxB, cyB, czB, sx, ox, sy, oy, c, oB0, oB1, oB2, wB0, wB1, wB2);

    uint4 qA0 = __ldg(&g_planes_q[oA0]);
    uint4 qA1 = __ldg(&g_planes_q[oA1]);
    uint4 qA2 = __ldg(&g_planes_q[oA2]);
    uint4 qB0 = __ldg(&g_planes_q[oB0]);
    uint4 qB1 = __ldg(&g_planes_q[oB1]);
    uint4 qB2 = __ldg(&g_planes_q[oB2]);

    __half2 z = __float2half2_rn(0.f);
    __half2 accA[4] = { z, z, z, z };
    __half2 accB[4] = { z, z, z, z };
    fma_quad(accA, qA0, wA0);
    fma_quad(accA, qA1, wA1);
    fma_quad(accA, qA2, wA2);
    fma_quad(accB, qB0, wB0);
    fma_quad(accB, qB1, wB1);
    fma_quad(accB, qB2, wB2);

    // quad butterfly reduction in half2 (8 shfl+hadd2 per point)
    #pragma unroll
    for (int r = 0; r < 4; r++) {
        accA[r] = hshfl_add(accA[r], 1);
        accA[r] = hshfl_add(accA[r], 2);
        accB[r] = hshfl_add(accB[r], 1);
        accB[r] = hshfl_add(accB[r], 2);
    }

    // lane c writes float4 #c of the pair's 64B output record:
    // c=0: ptA ch0-3, c=1: ptA ch4-7, c=2: ptB ch0-3, c=3: ptB ch4-7
    __half2 s0 = (c & 2) ? accB[(c & 1) * 2]     : accA[(c & 1) * 2];
    __half2 s1 = (c & 2) ? accB[(c & 1) * 2 + 1] : accA[(c & 1) * 2 + 1];

    // clamp [-10,10] in half2, then upconvert (bias already folded into quads)
    const __half2 TEN  = __float2half2_rn(10.f);
    const __half2 NTEN = __float2half2_rn(-10.f);
    s0 = __hmax2(__hmin2(s0, TEN), NTEN);
    s1 = __hmax2(__hmin2(s1, TEN), NTEN);

    float2 f0 = __half22float2(s0);
    float2 f1 = __half22float2(s1);

    if (c < 2 || hasB)
        ((float4*)(out + 16 * (size_t)g))[c] = make_float4(f0.x, f0.y, f1.x, f1.y);
}

extern "C" void kernel_launch(void* const* d_in, const int* in_sizes, int n_in,
                              void* d_out, int out_size)
{
    const float* coords = (const float*)d_in[0];
    const float* pxy    = (const float*)d_in[1];
    const float* pxz    = (const float*)d_in[2];
    const float* pyz    = (const float*)d_in[3];
    const float* projw  = (const float*)d_in[4];
    const float* projb  = (const float*)d_in[5];
    float* out = (float*)d_out;

    int N = in_sizes[0] / 3;

    dim3 qgrid(RES / 16, RES / 16, 3);
    build_quads_kernel<<<qgrid, 256>>>(pxy, pxz, pyz, projw, projb);

    long long pairs = (N + 1) / 2;
    long long threads = 4LL * pairs;
    int blocks = (int)((threads + 255) / 256);
    geo_encoder_kernel<<<blocks, 256>>>(coords, out, N);
}